// round 5
// baseline (speedup 1.0000x reference)
#include <cuda_runtime.h>
#include <cuda_fp16.h>
#include <cstdint>

// Problem dims (fixed)
#define T_TOK 2048
#define D_DIM 1024
#define H_DIM 4096
#define E_NUM 8
#define K2    (E_NUM * H_DIM)   // 32768
#define KSPLIT2 8

// GEMM tiling: CTA 128x256, warp 64x64, BK=32, 4-stage cp.async ring
#define BM 128
#define BN 256
#define BK 32
#define PADA 8    // halfs -> A row 40 halfs (80B)
#define PADB 8    // halfs -> B row 264 halfs (528B)
#define NSTAGE 4

#define A_STAGE_HALFS (BM * (BK + PADA))          // 5120
#define B_STAGE_HALFS (BK * (BN + PADB))          // 8448
#define STAGE_HALFS   (A_STAGE_HALFS + B_STAGE_HALFS)
#define SMEM_HALFS    (NSTAGE * STAGE_HALFS)
#define SMEM_BYTES    (SMEM_HALFS * 2)            // 108,544

// ---------------- scratch (static device arrays; no allocation) ----------------
__device__ __half g_xh [T_TOK * D_DIM];
__device__ __half g_w1h[(size_t)E_NUM * D_DIM * H_DIM]; // [e][k=D][n=H]
__device__ __half g_w2h[(size_t)E_NUM * H_DIM * D_DIM]; // flat [K2][D]
__device__ __half g_hb [(size_t)T_TOK * K2];            // probs*gelu(fc1), [t][k2]
__device__ float  g_probs[T_TOK * E_NUM];

// ---------------- fp32 -> fp16 conversion ----------------
template <int SEL>
__global__ void f2h_kernel(const float* __restrict__ src, int n) {
    __half* dst = (SEL == 0) ? g_xh : (SEL == 1) ? g_w1h : g_w2h;
    int i = (blockIdx.x * blockDim.x + threadIdx.x) * 4;
    if (i >= n) return;
    float4 v = *reinterpret_cast<const float4*>(src + i);
    *reinterpret_cast<__half2*>(dst + i)     = __floats2half2_rn(v.x, v.y);
    *reinterpret_cast<__half2*>(dst + i + 2) = __floats2half2_rn(v.z, v.w);
}

// ---------------- router: logits -> softmax probs ----------------
__global__ void router_kernel(const float* __restrict__ x,
                              const float* __restrict__ rw,
                              const float* __restrict__ rb,
                              float* __restrict__ dout_probs) {
    __shared__ float srw[E_NUM][D_DIM];   // transposed [e][d]: conflict-free
    int tid = threadIdx.x;
    for (int i = tid; i < D_DIM * E_NUM; i += 256) {
        int d = i >> 3, e = i & 7;
        srw[e][d] = rw[i];
    }
    __syncthreads();

    int gwarp = (blockIdx.x * blockDim.x + tid) >> 5;  // token id
    int lane  = tid & 31;
    if (gwarp >= T_TOK) return;
    const float* xr = x + (size_t)gwarp * D_DIM;
    float xv[32];
#pragma unroll
    for (int i = 0; i < 32; i++) xv[i] = xr[lane + 32 * i];

    float logit[E_NUM];
#pragma unroll
    for (int e = 0; e < E_NUM; e++) {
        float s = 0.f;
#pragma unroll
        for (int i = 0; i < 32; i++) s += xv[i] * srw[e][lane + 32 * i];
#pragma unroll
        for (int o = 16; o; o >>= 1) s += __shfl_xor_sync(0xffffffffu, s, o);
        logit[e] = s + rb[e];
    }
    if (lane == 0) {
        float m = logit[0];
#pragma unroll
        for (int e = 1; e < E_NUM; e++) m = fmaxf(m, logit[e]);
        float p[E_NUM], sum = 0.f;
#pragma unroll
        for (int e = 0; e < E_NUM; e++) { p[e] = expf(logit[e] - m); sum += p[e]; }
        float inv = 1.f / sum;
#pragma unroll
        for (int e = 0; e < E_NUM; e++) {
            float v = p[e] * inv;
            g_probs[gwarp * E_NUM + e]    = v;
            dout_probs[gwarp * E_NUM + e] = v;
        }
    }
}

// ---------------- out init: y = sum_e probs[t,e]*fc2_bias[e,:] ----------------
__global__ void init_out_kernel(const float* __restrict__ fc2b, float* __restrict__ y) {
    int i = blockIdx.x * blockDim.x + threadIdx.x;
    int t = i / D_DIM, d = i % D_DIM;
    float s = 0.f;
#pragma unroll
    for (int e = 0; e < E_NUM; e++) s += g_probs[t * E_NUM + e] * fc2b[e * D_DIM + d];
    y[i] = s;
}

__device__ __forceinline__ float gelu_exact(float v) {
    return 0.5f * v * (1.0f + erff(v * 0.70710678118654752f));
}

// ---------------- fused GEMMs (mma.sync m16n8k16 f32.f16) ----------------
// MODE 1: h'[t, e*H+n] = probs[t,e]*gelu(x@W1_e + b1_e)    A=g_xh, B=g_w1h[e]
// MODE 2: y[t,d] += h' @ W2flat  (split-K over blockIdx.z, atomicAdd)
template <int MODE>
__global__ __launch_bounds__(256, 1)
void gemm_kernel(const float* __restrict__ fc1b, float* __restrict__ yout) {
    extern __shared__ __half smem[];
    // stage s: A at smem + s*STAGE_HALFS, B at +A_STAGE_HALFS
    const int tid  = threadIdx.x;
    const int lane = tid & 31;
    const int warp = tid >> 5;
    const int wm = warp >> 2;   // 0..1 (64 rows)
    const int wn = warp & 3;    // 0..3 (64 cols)

    const int bn = blockIdx.x;
    const int bm = blockIdx.y;
    const int bz = blockIdx.z;

    const __half* A;
    const __half* B;
    size_t lda, ldb;
    int kIters;
    if (MODE == 1) {
        A = g_xh + (size_t)bm * BM * D_DIM;                 lda = D_DIM;
        B = g_w1h + (size_t)bz * D_DIM * H_DIM + bn * BN;   ldb = H_DIM;
        kIters = D_DIM / BK;                   // 32
    } else {
        const size_t kOff = (size_t)bz * (K2 / KSPLIT2);    // 4096 per split
        A = g_hb  + (size_t)bm * BM * K2 + kOff;            lda = K2;
        B = g_w2h + kOff * D_DIM + bn * BN;                 ldb = D_DIM;
        kIters = (K2 / KSPLIT2) / BK;          // 128
    }

    auto load_stage = [&](int s, int kt) {
        const int k0 = kt * BK;
        __half* As = smem + s * STAGE_HALFS;
        __half* Bs = As + A_STAGE_HALFS;
        // A: 128x32 halfs = 512 x 16B chunks
#pragma unroll
        for (int i = 0; i < 2; i++) {
            int c = tid + i * 256;
            int row = c >> 2, off = (c & 3) * 8;
            const __half* gp = A + (size_t)row * lda + k0 + off;
            unsigned sp = (unsigned)__cvta_generic_to_shared(As + row * (BK + PADA) + off);
            asm volatile("cp.async.cg.shared.global [%0], [%1], 16;" :: "r"(sp), "l"(gp));
        }
        // B: 32x256 halfs = 1024 x 16B chunks
#pragma unroll
        for (int i = 0; i < 4; i++) {
            int c = tid + i * 256;
            int row = c >> 5, off = (c & 31) * 8;
            const __half* gp = B + (size_t)(k0 + row) * ldb + off;
            unsigned sp = (unsigned)__cvta_generic_to_shared(Bs + row * (BN + PADB) + off);
            asm volatile("cp.async.cg.shared.global [%0], [%1], 16;" :: "r"(sp), "l"(gp));
        }
        asm volatile("cp.async.commit_group;" ::);
    };

    float acc[4][8][4];
#pragma unroll
    for (int mf = 0; mf < 4; mf++)
#pragma unroll
        for (int nf = 0; nf < 8; nf++)
#pragma unroll
            for (int i = 0; i < 4; i++) acc[mf][nf][i] = 0.f;

    // prologue: stages 0..2
#pragma unroll
    for (int j = 0; j < NSTAGE - 1; j++) load_stage(j, j);

    for (int j = 0; j < kIters; j++) {
        asm volatile("cp.async.wait_group 2;" ::);
        __syncthreads();   // stage j ready for all; all warps done with stage (j-1)&3

        const int p = j + NSTAGE - 1;
        if (p < kIters) load_stage(p & 3, p);   // writes (j-1)&3 — safe after sync
        else asm volatile("cp.async.commit_group;" ::);  // keep group count aligned

        const __half* As = smem + (j & 3) * STAGE_HALFS;
        const __half* Bs = As + A_STAGE_HALFS;

#pragma unroll
        for (int ks = 0; ks < 2; ks++) {
            const int kb = ks * 16;
            unsigned a[4][4];
            unsigned b[8][2];
#pragma unroll
            for (int mf = 0; mf < 4; mf++) {
                int mrow = wm * 64 + mf * 16 + (lane & 15);
                unsigned addr = (unsigned)__cvta_generic_to_shared(
                    As + mrow * (BK + PADA) + kb + (lane >> 4) * 8);
                asm volatile("ldmatrix.sync.aligned.m8n8.x4.shared.b16 {%0,%1,%2,%3}, [%4];"
                             : "=r"(a[mf][0]), "=r"(a[mf][1]), "=r"(a[mf][2]), "=r"(a[mf][3])
                             : "r"(addr));
            }
#pragma unroll
            for (int nf4 = 0; nf4 < 4; nf4++) {
                int ncol = wn * 64 + nf4 * 16 + (lane >> 4) * 8;
                unsigned r0, r1, r2, r3;
                unsigned addr = (unsigned)__cvta_generic_to_shared(
                    Bs + (kb + (lane & 15)) * (BN + PADB) + ncol);
                asm volatile("ldmatrix.sync.aligned.m8n8.x4.trans.shared.b16 {%0,%1,%2,%3}, [%4];"
                             : "=r"(r0), "=r"(r1), "=r"(r2), "=r"(r3)
                             : "r"(addr));
                b[nf4 * 2][0]     = r0; b[nf4 * 2][1]     = r1;
                b[nf4 * 2 + 1][0] = r2; b[nf4 * 2 + 1][1] = r3;
            }
#pragma unroll
            for (int mf = 0; mf < 4; mf++)
#pragma unroll
                for (int nf = 0; nf < 8; nf++) {
                    asm volatile(
                        "mma.sync.aligned.m16n8k16.row.col.f32.f16.f16.f32 "
                        "{%0,%1,%2,%3}, {%4,%5,%6,%7}, {%8,%9}, {%0,%1,%2,%3};"
                        : "+f"(acc[mf][nf][0]), "+f"(acc[mf][nf][1]),
                          "+f"(acc[mf][nf][2]), "+f"(acc[mf][nf][3])
                        : "r"(a[mf][0]), "r"(a[mf][1]), "r"(a[mf][2]), "r"(a[mf][3]),
                          "r"(b[nf][0]), "r"(b[nf][1]));
                }
        }
        __syncthreads();   // NOTE: needed? prefetch of iter j+1 targets (j)&3? No:
        // iter j+1 prefetches (j+4)&3 == (j)&3 — the stage we just read. The top
        // sync of iter j+1 alone orders that, so this sync is redundant... but the
        // top sync of j+1 IS hit by every warp before its prefetch. Remove:
    }
    // (second __syncthreads intentionally kept out of the hot path — see top sync)

    // ---------------- epilogue ----------------
    const int mBase = bm * BM + wm * 64;
    const int nBase = bn * BN + wn * 64;
    if (MODE == 1) {
        const int e = bz;
#pragma unroll
        for (int mf = 0; mf < 4; mf++) {
            int r0 = mBase + mf * 16 + (lane >> 2);
#pragma unroll
            for (int nf = 0; nf < 8; nf++) {
                int c0 = nBase + nf * 8 + (lane & 3) * 2;
                float bb0 = fc1b[(size_t)e * H_DIM + c0];
                float bb1 = fc1b[(size_t)e * H_DIM + c0 + 1];
#pragma unroll
                for (int h = 0; h < 2; h++) {
                    int r = r0 + h * 8;
                    float p = g_probs[r * E_NUM + e];
                    float v0 = gelu_exact(acc[mf][nf][h * 2 + 0] + bb0) * p;
                    float v1 = gelu_exact(acc[mf][nf][h * 2 + 1] + bb1) * p;
                    *reinterpret_cast<__half2*>(
                        &g_hb[(size_t)r * K2 + (size_t)e * H_DIM + c0]) =
                        __floats2half2_rn(v0, v1);
                }
            }
        }
    } else {
#pragma unroll
        for (int mf = 0; mf < 4; mf++) {
            int r0 = mBase + mf * 16 + (lane >> 2);
#pragma unroll
            for (int nf = 0; nf < 8; nf++) {
                int c0 = nBase + nf * 8 + (lane & 3) * 2;
                atomicAdd(&yout[(size_t)r0 * D_DIM + c0],           acc[mf][nf][0]);
                atomicAdd(&yout[(size_t)r0 * D_DIM + c0 + 1],       acc[mf][nf][1]);
                atomicAdd(&yout[(size_t)(r0 + 8) * D_DIM + c0],     acc[mf][nf][2]);
                atomicAdd(&yout[(size_t)(r0 + 8) * D_DIM + c0 + 1], acc[mf][nf][3]);
            }
        }
    }
}

// ---------------- launch ----------------
extern "C" void kernel_launch(void* const* d_in, const int* in_sizes, int n_in,
                              void* d_out, int out_size) {
    const float* x   = (const float*)d_in[0];
    const float* rw  = (const float*)d_in[1];
    const float* rb  = (const float*)d_in[2];
    const float* w1  = (const float*)d_in[3];
    const float* b1  = (const float*)d_in[4];
    const float* w2  = (const float*)d_in[5];
    const float* b2  = (const float*)d_in[6];

    float* y      = (float*)d_out;                 // [T, D]
    float* dprobs = y + (size_t)T_TOK * D_DIM;     // [T, E]

    static bool attr_set = false;
    // (cudaFuncSetAttribute is idempotent host-side configuration, not memory
    //  allocation; call unconditionally to stay stateless.)
    cudaFuncSetAttribute(gemm_kernel<1>, cudaFuncAttributeMaxDynamicSharedMemorySize, SMEM_BYTES);
    cudaFuncSetAttribute(gemm_kernel<2>, cudaFuncAttributeMaxDynamicSharedMemorySize, SMEM_BYTES);
    (void)attr_set;

    const int nX = T_TOK * D_DIM;                  // 2,097,152
    const int nW = E_NUM * D_DIM * H_DIM;          // 33,554,432

    f2h_kernel<0><<<nX / 4 / 256, 256>>>(x, nX);
    f2h_kernel<1><<<nW / 4 / 256, 256>>>(w1, nW);
    f2h_kernel<2><<<nW / 4 / 256, 256>>>(w2, nW);

    router_kernel<<<T_TOK / 8, 256>>>(x, rw, rb, dprobs);
    init_out_kernel<<<(T_TOK * D_DIM) / 256, 256>>>(b2, y);

    {
        dim3 g(H_DIM / BN, T_TOK / BM, E_NUM);     // (16, 16, 8) = 2048 CTAs
        gemm_kernel<1><<<g, 256, SMEM_BYTES>>>(b1, nullptr);
    }
    {
        dim3 g(D_DIM / BN, T_TOK / BM, KSPLIT2);   // (4, 16, 8) = 512 CTAs
        gemm_kernel<2><<<g, 256, SMEM_BYTES>>>(nullptr, y);
    }
}

// round 6
// speedup vs baseline: 1.1411x; 1.1411x over previous
#include <cuda_runtime.h>
#include <cuda_fp16.h>
#include <cstdint>

// Problem dims (fixed)
#define T_TOK 2048
#define D_DIM 1024
#define H_DIM 4096
#define E_NUM 8
#define K2    (E_NUM * H_DIM)   // 32768
#define KSPLIT2 4

// GEMM tiling: CTA 128x128, warp 64x32, BK=32, 4-stage cp.async ring, 2 CTAs/SM
#define BM 128
#define BN 128
#define BK 32
#define PADA 8    // A row = 40 halfs (80B)
#define PADB 8    // B row = 136 halfs (272B)
#define NSTAGE 4

#define A_STAGE_HALFS (BM * (BK + PADA))          // 5120
#define B_STAGE_HALFS (BK * (BN + PADB))          // 4352
#define STAGE_HALFS   (A_STAGE_HALFS + B_STAGE_HALFS)  // 9472
#define SMEM_BYTES    (NSTAGE * STAGE_HALFS * 2)  // 75,776

// ---------------- scratch (static device arrays; no allocation) ----------------
__device__ __half g_xh [T_TOK * D_DIM];
__device__ __half g_w1h[(size_t)E_NUM * D_DIM * H_DIM]; // [e][k=D][n=H]
__device__ __half g_w2h[(size_t)E_NUM * H_DIM * D_DIM]; // flat [K2][D]
__device__ __half g_hb [(size_t)T_TOK * K2];            // probs*gelu(fc1), [t][k2]
__device__ float  g_probs[T_TOK * E_NUM];

// ---------------- fp32 -> fp16 conversion ----------------
template <int SEL>
__global__ void f2h_kernel(const float* __restrict__ src, int n) {
    __half* dst = (SEL == 0) ? g_xh : (SEL == 1) ? g_w1h : g_w2h;
    int i = (blockIdx.x * blockDim.x + threadIdx.x) * 4;
    if (i >= n) return;
    float4 v = *reinterpret_cast<const float4*>(src + i);
    *reinterpret_cast<__half2*>(dst + i)     = __floats2half2_rn(v.x, v.y);
    *reinterpret_cast<__half2*>(dst + i + 2) = __floats2half2_rn(v.z, v.w);
}

// ---------------- router: logits -> softmax probs ----------------
__global__ void router_kernel(const float* __restrict__ x,
                              const float* __restrict__ rw,
                              const float* __restrict__ rb,
                              float* __restrict__ dout_probs) {
    __shared__ float srw[E_NUM][D_DIM];   // transposed [e][d]: conflict-free
    int tid = threadIdx.x;
    for (int i = tid; i < D_DIM * E_NUM; i += 256) {
        int d = i >> 3, e = i & 7;
        srw[e][d] = rw[i];
    }
    __syncthreads();

    int gwarp = (blockIdx.x * blockDim.x + tid) >> 5;  // token id
    int lane  = tid & 31;
    if (gwarp >= T_TOK) return;
    const float* xr = x + (size_t)gwarp * D_DIM;
    float xv[32];
#pragma unroll
    for (int i = 0; i < 32; i++) xv[i] = xr[lane + 32 * i];

    float logit[E_NUM];
#pragma unroll
    for (int e = 0; e < E_NUM; e++) {
        float s = 0.f;
#pragma unroll
        for (int i = 0; i < 32; i++) s += xv[i] * srw[e][lane + 32 * i];
#pragma unroll
        for (int o = 16; o; o >>= 1) s += __shfl_xor_sync(0xffffffffu, s, o);
        logit[e] = s + rb[e];
    }
    if (lane == 0) {
        float m = logit[0];
#pragma unroll
        for (int e = 1; e < E_NUM; e++) m = fmaxf(m, logit[e]);
        float p[E_NUM], sum = 0.f;
#pragma unroll
        for (int e = 0; e < E_NUM; e++) { p[e] = expf(logit[e] - m); sum += p[e]; }
        float inv = 1.f / sum;
#pragma unroll
        for (int e = 0; e < E_NUM; e++) {
            float v = p[e] * inv;
            g_probs[gwarp * E_NUM + e]    = v;
            dout_probs[gwarp * E_NUM + e] = v;
        }
    }
}

// ---------------- out init: y = sum_e probs[t,e]*fc2_bias[e,:] ----------------
__global__ void init_out_kernel(const float* __restrict__ fc2b, float* __restrict__ y) {
    int i = blockIdx.x * blockDim.x + threadIdx.x;
    int t = i / D_DIM, d = i % D_DIM;
    float s = 0.f;
#pragma unroll
    for (int e = 0; e < E_NUM; e++) s += g_probs[t * E_NUM + e] * fc2b[e * D_DIM + d];
    y[i] = s;
}

__device__ __forceinline__ float gelu_exact(float v) {
    return 0.5f * v * (1.0f + erff(v * 0.70710678118654752f));
}

// ---------------- fused GEMMs (mma.sync m16n8k16 f32.f16) ----------------
// MODE 1: h'[t, e*H+n] = probs[t,e]*gelu(x@W1_e + b1_e)    A=g_xh, B=g_w1h[e]
// MODE 2: y[t,d] += h' @ W2flat  (split-K over blockIdx.z, atomicAdd)
template <int MODE>
__global__ __launch_bounds__(256, 2)
void gemm_kernel(const float* __restrict__ fc1b, float* __restrict__ yout) {
    extern __shared__ __half smem[];
    const int tid  = threadIdx.x;
    const int lane = tid & 31;
    const int warp = tid >> 5;
    const int wm = warp >> 2;   // 0..1 (64 rows)
    const int wn = warp & 3;    // 0..3 (32 cols)

    const int bn = blockIdx.x;
    const int bm = blockIdx.y;
    const int bz = blockIdx.z;

    const __half* A;
    const __half* B;
    size_t lda, ldb;
    int kIters;
    if (MODE == 1) {
        A = g_xh + (size_t)bm * BM * D_DIM;                 lda = D_DIM;
        B = g_w1h + (size_t)bz * D_DIM * H_DIM + bn * BN;   ldb = H_DIM;
        kIters = D_DIM / BK;                   // 32
    } else {
        const size_t kOff = (size_t)bz * (K2 / KSPLIT2);    // 8192 per split
        A = g_hb  + (size_t)bm * BM * K2 + kOff;            lda = K2;
        B = g_w2h + kOff * D_DIM + bn * BN;                 ldb = D_DIM;
        kIters = (K2 / KSPLIT2) / BK;          // 256
    }

    auto load_stage = [&](int s, int kt) {
        const int k0 = kt * BK;
        __half* As = smem + s * STAGE_HALFS;
        __half* Bs = As + A_STAGE_HALFS;
        // A: 128x32 halfs = 512 x 16B chunks
#pragma unroll
        for (int i = 0; i < 2; i++) {
            int c = tid + i * 256;
            int row = c >> 2, off = (c & 3) * 8;
            const __half* gp = A + (size_t)row * lda + k0 + off;
            unsigned sp = (unsigned)__cvta_generic_to_shared(As + row * (BK + PADA) + off);
            asm volatile("cp.async.cg.shared.global [%0], [%1], 16;" :: "r"(sp), "l"(gp));
        }
        // B: 32x128 halfs = 512 x 16B chunks
#pragma unroll
        for (int i = 0; i < 2; i++) {
            int c = tid + i * 256;
            int row = c >> 4, off = (c & 15) * 8;
            const __half* gp = B + (size_t)(k0 + row) * ldb + off;
            unsigned sp = (unsigned)__cvta_generic_to_shared(Bs + row * (BN + PADB) + off);
            asm volatile("cp.async.cg.shared.global [%0], [%1], 16;" :: "r"(sp), "l"(gp));
        }
        asm volatile("cp.async.commit_group;" ::);
    };

    float acc[4][4][4];
#pragma unroll
    for (int mf = 0; mf < 4; mf++)
#pragma unroll
        for (int nf = 0; nf < 4; nf++)
#pragma unroll
            for (int i = 0; i < 4; i++) acc[mf][nf][i] = 0.f;

    // prologue: stages 0..2
#pragma unroll
    for (int j = 0; j < NSTAGE - 1; j++) load_stage(j, j);

    for (int j = 0; j < kIters; j++) {
        asm volatile("cp.async.wait_group 2;" ::);
        __syncthreads();   // stage j&3 visible to all; all warps done reading (j-1)&3

        const int p = j + NSTAGE - 1;          // prefetch into stage (j-1)&3
        if (p < kIters) load_stage(p & 3, p);
        else asm volatile("cp.async.commit_group;" ::);  // keep group count aligned

        const __half* As = smem + (j & 3) * STAGE_HALFS;
        const __half* Bs = As + A_STAGE_HALFS;

#pragma unroll
        for (int ks = 0; ks < 2; ks++) {
            const int kb = ks * 16;
            unsigned a[4][4];
            unsigned b[4][2];
#pragma unroll
            for (int mf = 0; mf < 4; mf++) {
                int mrow = wm * 64 + mf * 16 + (lane & 15);
                unsigned addr = (unsigned)__cvta_generic_to_shared(
                    As + mrow * (BK + PADA) + kb + (lane >> 4) * 8);
                asm volatile("ldmatrix.sync.aligned.m8n8.x4.shared.b16 {%0,%1,%2,%3}, [%4];"
                             : "=r"(a[mf][0]), "=r"(a[mf][1]), "=r"(a[mf][2]), "=r"(a[mf][3])
                             : "r"(addr));
            }
#pragma unroll
            for (int nf2 = 0; nf2 < 2; nf2++) {
                int ncol = wn * 32 + nf2 * 16 + (lane >> 4) * 8;
                unsigned r0, r1, r2, r3;
                unsigned addr = (unsigned)__cvta_generic_to_shared(
                    Bs + (kb + (lane & 15)) * (BN + PADB) + ncol);
                asm volatile("ldmatrix.sync.aligned.m8n8.x4.trans.shared.b16 {%0,%1,%2,%3}, [%4];"
                             : "=r"(r0), "=r"(r1), "=r"(r2), "=r"(r3)
                             : "r"(addr));
                b[nf2 * 2][0]     = r0; b[nf2 * 2][1]     = r1;
                b[nf2 * 2 + 1][0] = r2; b[nf2 * 2 + 1][1] = r3;
            }
#pragma unroll
            for (int mf = 0; mf < 4; mf++)
#pragma unroll
                for (int nf = 0; nf < 4; nf++) {
                    asm volatile(
                        "mma.sync.aligned.m16n8k16.row.col.f32.f16.f16.f32 "
                        "{%0,%1,%2,%3}, {%4,%5,%6,%7}, {%8,%9}, {%0,%1,%2,%3};"
                        : "+f"(acc[mf][nf][0]), "+f"(acc[mf][nf][1]),
                          "+f"(acc[mf][nf][2]), "+f"(acc[mf][nf][3])
                        : "r"(a[mf][0]), "r"(a[mf][1]), "r"(a[mf][2]), "r"(a[mf][3]),
                          "r"(b[nf][0]), "r"(b[nf][1]));
                }
        }
        // no bottom sync: next iter's top sync orders stage reuse
    }

    // ---------------- epilogue ----------------
    const int mBase = bm * BM + wm * 64;
    const int nBase = bn * BN + wn * 32;
    if (MODE == 1) {
        const int e = bz;
#pragma unroll
        for (int mf = 0; mf < 4; mf++) {
            int r0 = mBase + mf * 16 + (lane >> 2);
#pragma unroll
            for (int nf = 0; nf < 4; nf++) {
                int c0 = nBase + nf * 8 + (lane & 3) * 2;
                float bb0 = fc1b[(size_t)e * H_DIM + c0];
                float bb1 = fc1b[(size_t)e * H_DIM + c0 + 1];
#pragma unroll
                for (int h = 0; h < 2; h++) {
                    int r = r0 + h * 8;
                    float p = g_probs[r * E_NUM + e];
                    float v0 = gelu_exact(acc[mf][nf][h * 2 + 0] + bb0) * p;
                    float v1 = gelu_exact(acc[mf][nf][h * 2 + 1] + bb1) * p;
                    *reinterpret_cast<__half2*>(
                        &g_hb[(size_t)r * K2 + (size_t)e * H_DIM + c0]) =
                        __floats2half2_rn(v0, v1);
                }
            }
        }
    } else {
#pragma unroll
        for (int mf = 0; mf < 4; mf++) {
            int r0 = mBase + mf * 16 + (lane >> 2);
#pragma unroll
            for (int nf = 0; nf < 4; nf++) {
                int c0 = nBase + nf * 8 + (lane & 3) * 2;
                atomicAdd(&yout[(size_t)r0 * D_DIM + c0],           acc[mf][nf][0]);
                atomicAdd(&yout[(size_t)r0 * D_DIM + c0 + 1],       acc[mf][nf][1]);
                atomicAdd(&yout[(size_t)(r0 + 8) * D_DIM + c0],     acc[mf][nf][2]);
                atomicAdd(&yout[(size_t)(r0 + 8) * D_DIM + c0 + 1], acc[mf][nf][3]);
            }
        }
    }
}

// ---------------- launch ----------------
extern "C" void kernel_launch(void* const* d_in, const int* in_sizes, int n_in,
                              void* d_out, int out_size) {
    const float* x   = (const float*)d_in[0];
    const float* rw  = (const float*)d_in[1];
    const float* rb  = (const float*)d_in[2];
    const float* w1  = (const float*)d_in[3];
    const float* b1  = (const float*)d_in[4];
    const float* w2  = (const float*)d_in[5];
    const float* b2  = (const float*)d_in[6];

    float* y      = (float*)d_out;                 // [T, D]
    float* dprobs = y + (size_t)T_TOK * D_DIM;     // [T, E]

    cudaFuncSetAttribute(gemm_kernel<1>, cudaFuncAttributeMaxDynamicSharedMemorySize, SMEM_BYTES);
    cudaFuncSetAttribute(gemm_kernel<2>, cudaFuncAttributeMaxDynamicSharedMemorySize, SMEM_BYTES);

    const int nX = T_TOK * D_DIM;                  // 2,097,152
    const int nW = E_NUM * D_DIM * H_DIM;          // 33,554,432

    f2h_kernel<0><<<nX / 4 / 256, 256>>>(x, nX);
    f2h_kernel<1><<<nW / 4 / 256, 256>>>(w1, nW);
    f2h_kernel<2><<<nW / 4 / 256, 256>>>(w2, nW);

    router_kernel<<<T_TOK / 8, 256>>>(x, rw, rb, dprobs);
    init_out_kernel<<<(T_TOK * D_DIM) / 256, 256>>>(b2, y);

    {
        dim3 g(H_DIM / BN, T_TOK / BM, E_NUM);     // (32, 16, 8) = 4096 CTAs
        gemm_kernel<1><<<g, 256, SMEM_BYTES>>>(b1, nullptr);
    }
    {
        dim3 g(D_DIM / BN, T_TOK / BM, KSPLIT2);   // (8, 16, 4) = 512 CTAs
        gemm_kernel<2><<<g, 256, SMEM_BYTES>>>(nullptr, y);
    }
}

// round 7
// speedup vs baseline: 1.2465x; 1.0924x over previous
#include <cuda_runtime.h>
#include <cuda_fp16.h>
#include <cstdint>

// Problem dims (fixed)
#define T_TOK 2048
#define D_DIM 1024
#define H_DIM 4096
#define E_NUM 8
#define K2    (E_NUM * H_DIM)   // 32768

// GEMM2 split-K: 7 uneven chunks (6 x 4672 + 1 x 4736), 128 tiles x 7 = 896 CTAs (~3.03 waves)
#define KSPLIT2 7
#define KCHUNK  4672            // 146 * 32

// GEMM tiling: CTA 128x128, warp 64x32, BK=32, 4-stage cp.async ring, 2 CTAs/SM
#define BM 128
#define BN 128
#define BK 32
#define PADA 8    // A row = 40 halfs (80B)
#define PADB 8    // B row = 136 halfs (272B)
#define NSTAGE 4

#define A_STAGE_HALFS (BM * (BK + PADA))               // 5120
#define B_STAGE_HALFS (BK * (BN + PADB))               // 4352
#define STAGE_HALFS   (A_STAGE_HALFS + B_STAGE_HALFS)  // 9472
#define SMEM_BYTES    (NSTAGE * STAGE_HALFS * 2)       // 75,776

// ---------------- scratch (static device arrays; no allocation) ----------------
__device__ __half g_xh [T_TOK * D_DIM];
__device__ __half g_w1h[(size_t)E_NUM * D_DIM * H_DIM]; // [e][k=D][n=H]
__device__ __half g_w2h[(size_t)E_NUM * H_DIM * D_DIM]; // flat [K2][D]
__device__ __half g_hb [(size_t)T_TOK * K2];            // probs*gelu(fc1), [t][k2]
__device__ float  g_probs[T_TOK * E_NUM];
__device__ float  g_part[(size_t)KSPLIT2 * T_TOK * D_DIM]; // GEMM2 split-K partials

// ---------------- fp32 -> fp16 conversion ----------------
template <int SEL>
__global__ void f2h_kernel(const float* __restrict__ src, int n) {
    __half* dst = (SEL == 0) ? g_xh : (SEL == 1) ? g_w1h : g_w2h;
    int i = (blockIdx.x * blockDim.x + threadIdx.x) * 4;
    if (i >= n) return;
    float4 v = *reinterpret_cast<const float4*>(src + i);
    *reinterpret_cast<__half2*>(dst + i)     = __floats2half2_rn(v.x, v.y);
    *reinterpret_cast<__half2*>(dst + i + 2) = __floats2half2_rn(v.z, v.w);
}

// ---------------- router: logits -> softmax probs ----------------
__global__ void router_kernel(const float* __restrict__ x,
                              const float* __restrict__ rw,
                              const float* __restrict__ rb,
                              float* __restrict__ dout_probs) {
    __shared__ float srw[E_NUM][D_DIM];   // transposed [e][d]: conflict-free
    int tid = threadIdx.x;
    for (int i = tid; i < D_DIM * E_NUM; i += 256) {
        int d = i >> 3, e = i & 7;
        srw[e][d] = rw[i];
    }
    __syncthreads();

    int gwarp = (blockIdx.x * blockDim.x + tid) >> 5;  // token id
    int lane  = tid & 31;
    if (gwarp >= T_TOK) return;
    const float* xr = x + (size_t)gwarp * D_DIM;
    float xv[32];
#pragma unroll
    for (int i = 0; i < 32; i++) xv[i] = xr[lane + 32 * i];

    float logit[E_NUM];
#pragma unroll
    for (int e = 0; e < E_NUM; e++) {
        float s = 0.f;
#pragma unroll
        for (int i = 0; i < 32; i++) s += xv[i] * srw[e][lane + 32 * i];
#pragma unroll
        for (int o = 16; o; o >>= 1) s += __shfl_xor_sync(0xffffffffu, s, o);
        logit[e] = s + rb[e];
    }
    if (lane == 0) {
        float m = logit[0];
#pragma unroll
        for (int e = 1; e < E_NUM; e++) m = fmaxf(m, logit[e]);
        float p[E_NUM], sum = 0.f;
#pragma unroll
        for (int e = 0; e < E_NUM; e++) { p[e] = expf(logit[e] - m); sum += p[e]; }
        float inv = 1.f / sum;
#pragma unroll
        for (int e = 0; e < E_NUM; e++) {
            float v = p[e] * inv;
            g_probs[gwarp * E_NUM + e]    = v;
            dout_probs[gwarp * E_NUM + e] = v;
        }
    }
}

__device__ __forceinline__ float gelu_exact(float v) {
    return 0.5f * v * (1.0f + erff(v * 0.70710678118654752f));
}

// ---------------- combine: y = sum_z part[z] + sum_e probs*fc2_bias ----------------
__global__ void combine_kernel(const float* __restrict__ fc2b, float* __restrict__ y) {
    int i = (blockIdx.x * blockDim.x + threadIdx.x) * 4;
    int t = i / D_DIM, d = i % D_DIM;
    float4 s = make_float4(0.f, 0.f, 0.f, 0.f);
#pragma unroll
    for (int e = 0; e < E_NUM; e++) {
        float p = g_probs[t * E_NUM + e];
        float4 b = *reinterpret_cast<const float4*>(&fc2b[(size_t)e * D_DIM + d]);
        s.x += p * b.x; s.y += p * b.y; s.z += p * b.z; s.w += p * b.w;
    }
#pragma unroll
    for (int z = 0; z < KSPLIT2; z++) {
        float4 v = *reinterpret_cast<const float4*>(&g_part[(size_t)z * T_TOK * D_DIM + i]);
        s.x += v.x; s.y += v.y; s.z += v.z; s.w += v.w;
    }
    *reinterpret_cast<float4*>(&y[i]) = s;
}

// ---------------- fused GEMMs (mma.sync m16n8k16 f32.f16) ----------------
// MODE 1: h'[t, e*H+n] = probs[t,e]*gelu(x@W1_e + b1_e)    A=g_xh, B=g_w1h[e]
// MODE 2: part[z][t,d] = h'[:, zchunk] @ W2flat[zchunk, :]  (plain stores)
template <int MODE>
__global__ __launch_bounds__(256, 2)
void gemm_kernel(const float* __restrict__ fc1b) {
    extern __shared__ __half smem[];
    const int tid  = threadIdx.x;
    const int lane = tid & 31;
    const int warp = tid >> 5;
    const int wm = warp >> 2;   // 0..1 (64 rows)
    const int wn = warp & 3;    // 0..3 (32 cols)

    const int bn = blockIdx.x;
    const int bm = blockIdx.y;
    const int bz = blockIdx.z;

    const __half* A;
    const __half* B;
    size_t lda, ldb;
    int kIters;
    if (MODE == 1) {
        A = g_xh + (size_t)bm * BM * D_DIM;                 lda = D_DIM;
        B = g_w1h + (size_t)bz * D_DIM * H_DIM + bn * BN;   ldb = H_DIM;
        kIters = D_DIM / BK;                   // 32
    } else {
        const size_t kOff = (size_t)bz * KCHUNK;            // 4672 per split
        A = g_hb  + (size_t)bm * BM * K2 + kOff;            lda = K2;
        B = g_w2h + kOff * D_DIM + bn * BN;                 ldb = D_DIM;
        kIters = (bz == KSPLIT2 - 1)
                   ? (K2 - (KSPLIT2 - 1) * KCHUNK) / BK     // 148
                   : KCHUNK / BK;                           // 146
    }

    auto load_stage = [&](int s, int kt) {
        const int k0 = kt * BK;
        __half* As = smem + s * STAGE_HALFS;
        __half* Bs = As + A_STAGE_HALFS;
        // A: 128x32 halfs = 512 x 16B chunks
#pragma unroll
        for (int i = 0; i < 2; i++) {
            int c = tid + i * 256;
            int row = c >> 2, off = (c & 3) * 8;
            const __half* gp = A + (size_t)row * lda + k0 + off;
            unsigned sp = (unsigned)__cvta_generic_to_shared(As + row * (BK + PADA) + off);
            asm volatile("cp.async.cg.shared.global [%0], [%1], 16;" :: "r"(sp), "l"(gp));
        }
        // B: 32x128 halfs = 512 x 16B chunks
#pragma unroll
        for (int i = 0; i < 2; i++) {
            int c = tid + i * 256;
            int row = c >> 4, off = (c & 15) * 8;
            const __half* gp = B + (size_t)(k0 + row) * ldb + off;
            unsigned sp = (unsigned)__cvta_generic_to_shared(Bs + row * (BN + PADB) + off);
            asm volatile("cp.async.cg.shared.global [%0], [%1], 16;" :: "r"(sp), "l"(gp));
        }
        asm volatile("cp.async.commit_group;" ::);
    };

    float acc[4][4][4];
#pragma unroll
    for (int mf = 0; mf < 4; mf++)
#pragma unroll
        for (int nf = 0; nf < 4; nf++)
#pragma unroll
            for (int i = 0; i < 4; i++) acc[mf][nf][i] = 0.f;

    // prologue: stages 0..2
#pragma unroll
    for (int j = 0; j < NSTAGE - 1; j++) load_stage(j, j);

    for (int j = 0; j < kIters; j++) {
        asm volatile("cp.async.wait_group 2;" ::);
        __syncthreads();   // stage j&3 visible; all warps done reading (j-1)&3

        const int p = j + NSTAGE - 1;          // prefetch into stage (j-1)&3
        if (p < kIters) load_stage(p & 3, p);
        else asm volatile("cp.async.commit_group;" ::);  // keep group count aligned

        const __half* As = smem + (j & 3) * STAGE_HALFS;
        const __half* Bs = As + A_STAGE_HALFS;

#pragma unroll
        for (int ks = 0; ks < 2; ks++) {
            const int kb = ks * 16;
            unsigned a[4][4];
            unsigned b[4][2];
#pragma unroll
            for (int mf = 0; mf < 4; mf++) {
                int mrow = wm * 64 + mf * 16 + (lane & 15);
                unsigned addr = (unsigned)__cvta_generic_to_shared(
                    As + mrow * (BK + PADA) + kb + (lane >> 4) * 8);
                asm volatile("ldmatrix.sync.aligned.m8n8.x4.shared.b16 {%0,%1,%2,%3}, [%4];"
                             : "=r"(a[mf][0]), "=r"(a[mf][1]), "=r"(a[mf][2]), "=r"(a[mf][3])
                             : "r"(addr));
            }
#pragma unroll
            for (int nf2 = 0; nf2 < 2; nf2++) {
                int ncol = wn * 32 + nf2 * 16 + (lane >> 4) * 8;
                unsigned r0, r1, r2, r3;
                unsigned addr = (unsigned)__cvta_generic_to_shared(
                    Bs + (kb + (lane & 15)) * (BN + PADB) + ncol);
                asm volatile("ldmatrix.sync.aligned.m8n8.x4.trans.shared.b16 {%0,%1,%2,%3}, [%4];"
                             : "=r"(r0), "=r"(r1), "=r"(r2), "=r"(r3)
                             : "r"(addr));
                b[nf2 * 2][0]     = r0; b[nf2 * 2][1]     = r1;
                b[nf2 * 2 + 1][0] = r2; b[nf2 * 2 + 1][1] = r3;
            }
#pragma unroll
            for (int mf = 0; mf < 4; mf++)
#pragma unroll
                for (int nf = 0; nf < 4; nf++) {
                    asm volatile(
                        "mma.sync.aligned.m16n8k16.row.col.f32.f16.f16.f32 "
                        "{%0,%1,%2,%3}, {%4,%5,%6,%7}, {%8,%9}, {%0,%1,%2,%3};"
                        : "+f"(acc[mf][nf][0]), "+f"(acc[mf][nf][1]),
                          "+f"(acc[mf][nf][2]), "+f"(acc[mf][nf][3])
                        : "r"(a[mf][0]), "r"(a[mf][1]), "r"(a[mf][2]), "r"(a[mf][3]),
                          "r"(b[nf][0]), "r"(b[nf][1]));
                }
        }
        // no bottom sync: next iter's top sync orders stage reuse
    }

    // ---------------- epilogue ----------------
    const int mBase = bm * BM + wm * 64;
    const int nBase = bn * BN + wn * 32;
    if (MODE == 1) {
        const int e = bz;
#pragma unroll
        for (int mf = 0; mf < 4; mf++) {
            int r0 = mBase + mf * 16 + (lane >> 2);
#pragma unroll
            for (int nf = 0; nf < 4; nf++) {
                int c0 = nBase + nf * 8 + (lane & 3) * 2;
                float bb0 = fc1b[(size_t)e * H_DIM + c0];
                float bb1 = fc1b[(size_t)e * H_DIM + c0 + 1];
#pragma unroll
                for (int h = 0; h < 2; h++) {
                    int r = r0 + h * 8;
                    float p = g_probs[r * E_NUM + e];
                    float v0 = gelu_exact(acc[mf][nf][h * 2 + 0] + bb0) * p;
                    float v1 = gelu_exact(acc[mf][nf][h * 2 + 1] + bb1) * p;
                    *reinterpret_cast<__half2*>(
                        &g_hb[(size_t)r * K2 + (size_t)e * H_DIM + c0]) =
                        __floats2half2_rn(v0, v1);
                }
            }
        }
    } else {
        float* part = g_part + (size_t)bz * T_TOK * D_DIM;
#pragma unroll
        for (int mf = 0; mf < 4; mf++) {
            int r0 = mBase + mf * 16 + (lane >> 2);
#pragma unroll
            for (int nf = 0; nf < 4; nf++) {
                int c0 = nBase + nf * 8 + (lane & 3) * 2;
                *reinterpret_cast<float2*>(&part[(size_t)r0 * D_DIM + c0]) =
                    make_float2(acc[mf][nf][0], acc[mf][nf][1]);
                *reinterpret_cast<float2*>(&part[(size_t)(r0 + 8) * D_DIM + c0]) =
                    make_float2(acc[mf][nf][2], acc[mf][nf][3]);
            }
        }
    }
}

// ---------------- launch ----------------
extern "C" void kernel_launch(void* const* d_in, const int* in_sizes, int n_in,
                              void* d_out, int out_size) {
    const float* x   = (const float*)d_in[0];
    const float* rw  = (const float*)d_in[1];
    const float* rb  = (const float*)d_in[2];
    const float* w1  = (const float*)d_in[3];
    const float* b1  = (const float*)d_in[4];
    const float* w2  = (const float*)d_in[5];
    const float* b2  = (const float*)d_in[6];

    float* y      = (float*)d_out;                 // [T, D]
    float* dprobs = y + (size_t)T_TOK * D_DIM;     // [T, E]

    cudaFuncSetAttribute(gemm_kernel<1>, cudaFuncAttributeMaxDynamicSharedMemorySize, SMEM_BYTES);
    cudaFuncSetAttribute(gemm_kernel<2>, cudaFuncAttributeMaxDynamicSharedMemorySize, SMEM_BYTES);

    const int nX = T_TOK * D_DIM;                  // 2,097,152
    const int nW = E_NUM * D_DIM * H_DIM;          // 33,554,432

    f2h_kernel<0><<<nX / 4 / 256, 256>>>(x, nX);
    f2h_kernel<1><<<nW / 4 / 256, 256>>>(w1, nW);
    f2h_kernel<2><<<nW / 4 / 256, 256>>>(w2, nW);

    router_kernel<<<T_TOK / 8, 256>>>(x, rw, rb, dprobs);

    {
        dim3 g(H_DIM / BN, T_TOK / BM, E_NUM);     // (32, 16, 8) = 4096 CTAs
        gemm_kernel<1><<<g, 256, SMEM_BYTES>>>(b1);
    }
    {
        dim3 g(D_DIM / BN, T_TOK / BM, KSPLIT2);   // (8, 16, 7) = 896 CTAs
        gemm_kernel<2><<<g, 256, SMEM_BYTES>>>(nullptr);
    }
    combine_kernel<<<(T_TOK * D_DIM) / 4 / 256, 256>>>(b2, y);
}

// round 8
// speedup vs baseline: 1.2793x; 1.0263x over previous
#include <cuda_runtime.h>
#include <cuda_fp16.h>
#include <cstdint>

// Problem dims (fixed)
#define T_TOK 2048
#define D_DIM 1024
#define H_DIM 4096
#define E_NUM 8
#define K2    (E_NUM * H_DIM)   // 32768

// GEMM2 split-K: 7 uneven chunks (6 x 4672 + 1 x 4736), 128 tiles x 7 = 896 CTAs (~3.03 waves)
#define KSPLIT2 7
#define KCHUNK  4672            // 146 * 32

// GEMM tiling: CTA 128x128, warp 64x32, BK=32, 4-stage cp.async ring, 2 CTAs/SM
#define BM 128
#define BN 128
#define BK 32
#define PADA 8    // A row = 40 halfs (80B)
#define PADB 8    // B row = 136 halfs (272B)
#define NSTAGE 4

#define A_STAGE_HALFS (BM * (BK + PADA))               // 5120
#define B_STAGE_HALFS (BK * (BN + PADB))               // 4352
#define STAGE_HALFS   (A_STAGE_HALFS + B_STAGE_HALFS)  // 9472
#define SMEM_BYTES    (NSTAGE * STAGE_HALFS * 2)       // 75,776

#define NW1 (E_NUM * D_DIM * H_DIM)   // 33,554,432
#define NX  (T_TOK * D_DIM)           // 2,097,152

// ---------------- scratch (static device arrays; no allocation) ----------------
__device__ __half g_xh [NX];
__device__ __half g_w1h[(size_t)NW1];                   // [e][k=D][n=H]
__device__ __half g_w2h[(size_t)NW1];                   // flat [K2][D]
__device__ __half g_hb [(size_t)T_TOK * K2];            // probs*gelu(fc1), [t][k2]
__device__ float  g_probs[T_TOK * E_NUM];
__device__ float  g_part[(size_t)KSPLIT2 * T_TOK * D_DIM]; // GEMM2 split-K partials

// ---------------- prep: w1 + x fp32 -> fp16 (one launch) ----------------
// grid: 32768 blocks for w1 + 2048 blocks for x = 34816
__global__ void prep_kernel(const float* __restrict__ w1, const float* __restrict__ x) {
    int b = blockIdx.x;
    if (b < NW1 / 4 / 256) {
        int i = (b * 256 + threadIdx.x) * 4;
        float4 v = *reinterpret_cast<const float4*>(w1 + i);
        *reinterpret_cast<__half2*>(&g_w1h[i])     = __floats2half2_rn(v.x, v.y);
        *reinterpret_cast<__half2*>(&g_w1h[i + 2]) = __floats2half2_rn(v.z, v.w);
    } else {
        int i = ((b - NW1 / 4 / 256) * 256 + threadIdx.x) * 4;
        float4 v = *reinterpret_cast<const float4*>(x + i);
        *reinterpret_cast<__half2*>(&g_xh[i])     = __floats2half2_rn(v.x, v.y);
        *reinterpret_cast<__half2*>(&g_xh[i + 2]) = __floats2half2_rn(v.z, v.w);
    }
}

// ---------------- router: logits -> softmax probs ----------------
__global__ void router_kernel(const float* __restrict__ x,
                              const float* __restrict__ rw,
                              const float* __restrict__ rb,
                              float* __restrict__ dout_probs) {
    __shared__ float srw[E_NUM][D_DIM];   // transposed [e][d]: conflict-free
    int tid = threadIdx.x;
    for (int i = tid; i < D_DIM * E_NUM; i += 256) {
        int d = i >> 3, e = i & 7;
        srw[e][d] = rw[i];
    }
    __syncthreads();

    int gwarp = (blockIdx.x * blockDim.x + tid) >> 5;  // token id
    int lane  = tid & 31;
    if (gwarp >= T_TOK) return;
    const float* xr = x + (size_t)gwarp * D_DIM;
    float xv[32];
#pragma unroll
    for (int i = 0; i < 32; i++) xv[i] = xr[lane + 32 * i];

    float logit[E_NUM];
#pragma unroll
    for (int e = 0; e < E_NUM; e++) {
        float s = 0.f;
#pragma unroll
        for (int i = 0; i < 32; i++) s += xv[i] * srw[e][lane + 32 * i];
#pragma unroll
        for (int o = 16; o; o >>= 1) s += __shfl_xor_sync(0xffffffffu, s, o);
        logit[e] = s + rb[e];
    }
    if (lane == 0) {
        float m = logit[0];
#pragma unroll
        for (int e = 1; e < E_NUM; e++) m = fmaxf(m, logit[e]);
        float p[E_NUM], sum = 0.f;
#pragma unroll
        for (int e = 0; e < E_NUM; e++) { p[e] = expf(logit[e] - m); sum += p[e]; }
        float inv = 1.f / sum;
#pragma unroll
        for (int e = 0; e < E_NUM; e++) {
            float v = p[e] * inv;
            g_probs[gwarp * E_NUM + e]    = v;
            dout_probs[gwarp * E_NUM + e] = v;
        }
    }
}

__device__ __forceinline__ float gelu_exact(float v) {
    return 0.5f * v * (1.0f + erff(v * 0.70710678118654752f));
}

// ---------------- combine: y = sum_z part[z] + sum_e probs*fc2_bias ----------------
__global__ void combine_kernel(const float* __restrict__ fc2b, float* __restrict__ y) {
    int i = (blockIdx.x * blockDim.x + threadIdx.x) * 4;
    int t = i / D_DIM, d = i % D_DIM;
    float4 s = make_float4(0.f, 0.f, 0.f, 0.f);
#pragma unroll
    for (int e = 0; e < E_NUM; e++) {
        float p = g_probs[t * E_NUM + e];
        float4 b = *reinterpret_cast<const float4*>(&fc2b[(size_t)e * D_DIM + d]);
        s.x += p * b.x; s.y += p * b.y; s.z += p * b.z; s.w += p * b.w;
    }
#pragma unroll
    for (int z = 0; z < KSPLIT2; z++) {
        float4 v = *reinterpret_cast<const float4*>(&g_part[(size_t)z * T_TOK * D_DIM + i]);
        s.x += v.x; s.y += v.y; s.z += v.z; s.w += v.w;
    }
    *reinterpret_cast<float4*>(&y[i]) = s;
}

// ---------------- fused GEMMs (mma.sync m16n8k16 f32.f16) ----------------
// MODE 1: h'[t, e*H+n] = probs[t,e]*gelu(x@W1_e + b1_e); also converts its slice of w2
// MODE 2: part[z][t,d] = h'[:, zchunk] @ W2flat[zchunk, :]  (plain stores)
template <int MODE>
__global__ __launch_bounds__(256, 2)
void gemm_kernel(const float* __restrict__ fc1b, const float* __restrict__ w2src) {
    extern __shared__ __half smem[];
    const int tid  = threadIdx.x;
    const int lane = tid & 31;
    const int warp = tid >> 5;
    const int wm = warp >> 2;   // 0..1 (64 rows)
    const int wn = warp & 3;    // 0..3 (32 cols)

    const int bn = blockIdx.x;
    const int bm = blockIdx.y;
    const int bz = blockIdx.z;

    const __half* A;
    const __half* B;
    size_t lda, ldb;
    int kIters;
    if (MODE == 1) {
        A = g_xh + (size_t)bm * BM * D_DIM;                 lda = D_DIM;
        B = g_w1h + (size_t)bz * D_DIM * H_DIM + bn * BN;   ldb = H_DIM;
        kIters = D_DIM / BK;                   // 32
    } else {
        const size_t kOff = (size_t)bz * KCHUNK;            // 4672 per split
        A = g_hb  + (size_t)bm * BM * K2 + kOff;            lda = K2;
        B = g_w2h + kOff * D_DIM + bn * BN;                 ldb = D_DIM;
        kIters = (bz == KSPLIT2 - 1)
                   ? (K2 - (KSPLIT2 - 1) * KCHUNK) / BK     // 148
                   : KCHUNK / BK;                           // 146
    }

    auto load_stage = [&](int s, int kt) {
        const int k0 = kt * BK;
        __half* As = smem + s * STAGE_HALFS;
        __half* Bs = As + A_STAGE_HALFS;
        // A: 128x32 halfs = 512 x 16B chunks
#pragma unroll
        for (int i = 0; i < 2; i++) {
            int c = tid + i * 256;
            int row = c >> 2, off = (c & 3) * 8;
            const __half* gp = A + (size_t)row * lda + k0 + off;
            unsigned sp = (unsigned)__cvta_generic_to_shared(As + row * (BK + PADA) + off);
            asm volatile("cp.async.cg.shared.global [%0], [%1], 16;" :: "r"(sp), "l"(gp));
        }
        // B: 32x128 halfs = 512 x 16B chunks
#pragma unroll
        for (int i = 0; i < 2; i++) {
            int c = tid + i * 256;
            int row = c >> 4, off = (c & 15) * 8;
            const __half* gp = B + (size_t)(k0 + row) * ldb + off;
            unsigned sp = (unsigned)__cvta_generic_to_shared(Bs + row * (BN + PADB) + off);
            asm volatile("cp.async.cg.shared.global [%0], [%1], 16;" :: "r"(sp), "l"(gp));
        }
        asm volatile("cp.async.commit_group;" ::);
    };

    float acc[4][4][4];
#pragma unroll
    for (int mf = 0; mf < 4; mf++)
#pragma unroll
        for (int nf = 0; nf < 4; nf++)
#pragma unroll
            for (int i = 0; i < 4; i++) acc[mf][nf][i] = 0.f;

    // prologue: stages 0..2 (async; conversion below overlaps their flight time)
#pragma unroll
    for (int j = 0; j < NSTAGE - 1; j++) load_stage(j, j);

    if (MODE == 1) {
        // fused w2 fp32->fp16: this CTA's 8192-element slice (4096 CTAs cover 33.5M)
        const int cid = bn + 32 * (bm + 16 * bz);   // 0..4095
        const size_t base = (size_t)cid * 8192;
#pragma unroll
        for (int t = 0; t < 8; t++) {
            size_t i = base + (size_t)(tid + t * 256) * 4;
            float4 v = *reinterpret_cast<const float4*>(w2src + i);
            __half2 h0 = __floats2half2_rn(v.x, v.y);
            __half2 h1 = __floats2half2_rn(v.z, v.w);
            *reinterpret_cast<__half2*>(&g_w2h[i])     = h0;
            *reinterpret_cast<__half2*>(&g_w2h[i + 2]) = h1;
        }
    }

    for (int j = 0; j < kIters; j++) {
        asm volatile("cp.async.wait_group 2;" ::);
        __syncthreads();   // stage j&3 visible; all warps done reading (j-1)&3

        const int p = j + NSTAGE - 1;          // prefetch into stage (j-1)&3
        if (p < kIters) load_stage(p & 3, p);
        else asm volatile("cp.async.commit_group;" ::);  // keep group count aligned

        const __half* As = smem + (j & 3) * STAGE_HALFS;
        const __half* Bs = As + A_STAGE_HALFS;

#pragma unroll
        for (int ks = 0; ks < 2; ks++) {
            const int kb = ks * 16;
            unsigned a[4][4];
            unsigned b[4][2];
#pragma unroll
            for (int mf = 0; mf < 4; mf++) {
                int mrow = wm * 64 + mf * 16 + (lane & 15);
                unsigned addr = (unsigned)__cvta_generic_to_shared(
                    As + mrow * (BK + PADA) + kb + (lane >> 4) * 8);
                asm volatile("ldmatrix.sync.aligned.m8n8.x4.shared.b16 {%0,%1,%2,%3}, [%4];"
                             : "=r"(a[mf][0]), "=r"(a[mf][1]), "=r"(a[mf][2]), "=r"(a[mf][3])
                             : "r"(addr));
            }
#pragma unroll
            for (int nf2 = 0; nf2 < 2; nf2++) {
                int ncol = wn * 32 + nf2 * 16 + (lane >> 4) * 8;
                unsigned r0, r1, r2, r3;
                unsigned addr = (unsigned)__cvta_generic_to_shared(
                    Bs + (kb + (lane & 15)) * (BN + PADB) + ncol);
                asm volatile("ldmatrix.sync.aligned.m8n8.x4.trans.shared.b16 {%0,%1,%2,%3}, [%4];"
                             : "=r"(r0), "=r"(r1), "=r"(r2), "=r"(r3)
                             : "r"(addr));
                b[nf2 * 2][0]     = r0; b[nf2 * 2][1]     = r1;
                b[nf2 * 2 + 1][0] = r2; b[nf2 * 2 + 1][1] = r3;
            }
#pragma unroll
            for (int mf = 0; mf < 4; mf++)
#pragma unroll
                for (int nf = 0; nf < 4; nf++) {
                    asm volatile(
                        "mma.sync.aligned.m16n8k16.row.col.f32.f16.f16.f32 "
                        "{%0,%1,%2,%3}, {%4,%5,%6,%7}, {%8,%9}, {%0,%1,%2,%3};"
                        : "+f"(acc[mf][nf][0]), "+f"(acc[mf][nf][1]),
                          "+f"(acc[mf][nf][2]), "+f"(acc[mf][nf][3])
                        : "r"(a[mf][0]), "r"(a[mf][1]), "r"(a[mf][2]), "r"(a[mf][3]),
                          "r"(b[nf][0]), "r"(b[nf][1]));
                }
        }
        // no bottom sync: next iter's top sync orders stage reuse
    }

    // ---------------- epilogue ----------------
    const int mBase = bm * BM + wm * 64;
    const int nBase = bn * BN + wn * 32;
    if (MODE == 1) {
        const int e = bz;
#pragma unroll
        for (int mf = 0; mf < 4; mf++) {
            int r0 = mBase + mf * 16 + (lane >> 2);
#pragma unroll
            for (int nf = 0; nf < 4; nf++) {
                int c0 = nBase + nf * 8 + (lane & 3) * 2;
                float bb0 = fc1b[(size_t)e * H_DIM + c0];
                float bb1 = fc1b[(size_t)e * H_DIM + c0 + 1];
#pragma unroll
                for (int h = 0; h < 2; h++) {
                    int r = r0 + h * 8;
                    float p = g_probs[r * E_NUM + e];
                    float v0 = gelu_exact(acc[mf][nf][h * 2 + 0] + bb0) * p;
                    float v1 = gelu_exact(acc[mf][nf][h * 2 + 1] + bb1) * p;
                    *reinterpret_cast<__half2*>(
                        &g_hb[(size_t)r * K2 + (size_t)e * H_DIM + c0]) =
                        __floats2half2_rn(v0, v1);
                }
            }
        }
    } else {
        float* part = g_part + (size_t)bz * T_TOK * D_DIM;
#pragma unroll
        for (int mf = 0; mf < 4; mf++) {
            int r0 = mBase + mf * 16 + (lane >> 2);
#pragma unroll
            for (int nf = 0; nf < 4; nf++) {
                int c0 = nBase + nf * 8 + (lane & 3) * 2;
                *reinterpret_cast<float2*>(&part[(size_t)r0 * D_DIM + c0]) =
                    make_float2(acc[mf][nf][0], acc[mf][nf][1]);
                *reinterpret_cast<float2*>(&part[(size_t)(r0 + 8) * D_DIM + c0]) =
                    make_float2(acc[mf][nf][2], acc[mf][nf][3]);
            }
        }
    }
}

// ---------------- launch ----------------
extern "C" void kernel_launch(void* const* d_in, const int* in_sizes, int n_in,
                              void* d_out, int out_size) {
    const float* x   = (const float*)d_in[0];
    const float* rw  = (const float*)d_in[1];
    const float* rb  = (const float*)d_in[2];
    const float* w1  = (const float*)d_in[3];
    const float* b1  = (const float*)d_in[4];
    const float* w2  = (const float*)d_in[5];
    const float* b2  = (const float*)d_in[6];

    float* y      = (float*)d_out;                 // [T, D]
    float* dprobs = y + (size_t)T_TOK * D_DIM;     // [T, E]

    cudaFuncSetAttribute(gemm_kernel<1>, cudaFuncAttributeMaxDynamicSharedMemorySize, SMEM_BYTES);
    cudaFuncSetAttribute(gemm_kernel<2>, cudaFuncAttributeMaxDynamicSharedMemorySize, SMEM_BYTES);

    prep_kernel<<<NW1 / 4 / 256 + NX / 4 / 256, 256>>>(w1, x);   // w1 + x -> fp16
    router_kernel<<<T_TOK / 8, 256>>>(x, rw, rb, dprobs);

    {
        dim3 g(H_DIM / BN, T_TOK / BM, E_NUM);     // (32, 16, 8) = 4096 CTAs
        gemm_kernel<1><<<g, 256, SMEM_BYTES>>>(b1, w2);   // also converts w2
    }
    {
        dim3 g(D_DIM / BN, T_TOK / BM, KSPLIT2);   // (8, 16, 7) = 896 CTAs
        gemm_kernel<2><<<g, 256, SMEM_BYTES>>>(nullptr, nullptr);
    }
    combine_kernel<<<(T_TOK * D_DIM) / 4 / 256, 256>>>(b2, y);
}

// round 9
// speedup vs baseline: 1.3089x; 1.0232x over previous
#include <cuda_runtime.h>
#include <cuda_fp16.h>
#include <cstdint>

// Problem dims (fixed)
#define T_TOK 2048
#define D_DIM 1024
#define H_DIM 4096
#define E_NUM 8
#define K2    (E_NUM * H_DIM)   // 32768

// GEMM2 split-K: 7 uneven chunks (6 x 4672 + 1 x 4736), 128 tiles x 7 = 896 CTAs
#define KSPLIT2 7
#define KCHUNK  4672            // 73 * 64

// GEMM tiling: CTA 128x128, warp 64x32, BK=64, 3-stage cp.async ring, 2 CTAs/SM
#define BM 128
#define BN 128
#define BK 64
#define PADA 8    // A row = 72 halfs (144B)
#define PADB 8    // B row = 136 halfs (272B)
#define NSTAGE 3

#define A_STAGE_HALFS (BM * (BK + PADA))               // 9216
#define B_STAGE_HALFS (BK * (BN + PADB))               // 8704
#define STAGE_HALFS   (A_STAGE_HALFS + B_STAGE_HALFS)  // 17920
#define SMEM_BYTES    (NSTAGE * STAGE_HALFS * 2)       // 107,520

#define NW1 (E_NUM * D_DIM * H_DIM)   // 33,554,432
#define NX  (T_TOK * D_DIM)           // 2,097,152

// ---------------- scratch (static device arrays; no allocation) ----------------
__device__ __half g_xh [NX];
__device__ __half g_w1h[(size_t)NW1];                   // [e][k=D][n=H]
__device__ __half g_w2h[(size_t)NW1];                   // flat [K2][D]
__device__ __half g_hb [(size_t)T_TOK * K2];            // probs*gelu(fc1), [t][k2]
__device__ float  g_probs[T_TOK * E_NUM];
__device__ float  g_part[(size_t)KSPLIT2 * T_TOK * D_DIM]; // GEMM2 split-K partials

// ---------------- prep: w1 + x fp32 -> fp16 (one launch) ----------------
__global__ void prep_kernel(const float* __restrict__ w1, const float* __restrict__ x) {
    int b = blockIdx.x;
    if (b < NW1 / 4 / 256) {
        int i = (b * 256 + threadIdx.x) * 4;
        float4 v = *reinterpret_cast<const float4*>(w1 + i);
        *reinterpret_cast<__half2*>(&g_w1h[i])     = __floats2half2_rn(v.x, v.y);
        *reinterpret_cast<__half2*>(&g_w1h[i + 2]) = __floats2half2_rn(v.z, v.w);
    } else {
        int i = ((b - NW1 / 4 / 256) * 256 + threadIdx.x) * 4;
        float4 v = *reinterpret_cast<const float4*>(x + i);
        *reinterpret_cast<__half2*>(&g_xh[i])     = __floats2half2_rn(v.x, v.y);
        *reinterpret_cast<__half2*>(&g_xh[i + 2]) = __floats2half2_rn(v.z, v.w);
    }
}

// ---------------- router: logits -> softmax probs ----------------
__global__ void router_kernel(const float* __restrict__ x,
                              const float* __restrict__ rw,
                              const float* __restrict__ rb,
                              float* __restrict__ dout_probs) {
    __shared__ float srw[E_NUM][D_DIM];   // transposed [e][d]: conflict-free
    int tid = threadIdx.x;
    for (int i = tid; i < D_DIM * E_NUM; i += 256) {
        int d = i >> 3, e = i & 7;
        srw[e][d] = rw[i];
    }
    __syncthreads();

    int gwarp = (blockIdx.x * blockDim.x + tid) >> 5;  // token id
    int lane  = tid & 31;
    if (gwarp >= T_TOK) return;
    const float* xr = x + (size_t)gwarp * D_DIM;
    float xv[32];
#pragma unroll
    for (int i = 0; i < 32; i++) xv[i] = xr[lane + 32 * i];

    float logit[E_NUM];
#pragma unroll
    for (int e = 0; e < E_NUM; e++) {
        float s = 0.f;
#pragma unroll
        for (int i = 0; i < 32; i++) s += xv[i] * srw[e][lane + 32 * i];
#pragma unroll
        for (int o = 16; o; o >>= 1) s += __shfl_xor_sync(0xffffffffu, s, o);
        logit[e] = s + rb[e];
    }
    if (lane == 0) {
        float m = logit[0];
#pragma unroll
        for (int e = 1; e < E_NUM; e++) m = fmaxf(m, logit[e]);
        float p[E_NUM], sum = 0.f;
#pragma unroll
        for (int e = 0; e < E_NUM; e++) { p[e] = expf(logit[e] - m); sum += p[e]; }
        float inv = 1.f / sum;
#pragma unroll
        for (int e = 0; e < E_NUM; e++) {
            float v = p[e] * inv;
            g_probs[gwarp * E_NUM + e]    = v;
            dout_probs[gwarp * E_NUM + e] = v;
        }
    }
}

__device__ __forceinline__ float gelu_exact(float v) {
    return 0.5f * v * (1.0f + erff(v * 0.70710678118654752f));
}

// ---------------- combine: y = sum_z part[z] + sum_e probs*fc2_bias ----------------
__global__ void combine_kernel(const float* __restrict__ fc2b, float* __restrict__ y) {
    int i = (blockIdx.x * blockDim.x + threadIdx.x) * 4;
    int t = i / D_DIM, d = i % D_DIM;
    float4 s = make_float4(0.f, 0.f, 0.f, 0.f);
#pragma unroll
    for (int e = 0; e < E_NUM; e++) {
        float p = g_probs[t * E_NUM + e];
        float4 b = *reinterpret_cast<const float4*>(&fc2b[(size_t)e * D_DIM + d]);
        s.x += p * b.x; s.y += p * b.y; s.z += p * b.z; s.w += p * b.w;
    }
#pragma unroll
    for (int z = 0; z < KSPLIT2; z++) {
        float4 v = *reinterpret_cast<const float4*>(&g_part[(size_t)z * T_TOK * D_DIM + i]);
        s.x += v.x; s.y += v.y; s.z += v.z; s.w += v.w;
    }
    *reinterpret_cast<float4*>(&y[i]) = s;
}

// ---------------- fused GEMMs (mma.sync m16n8k16 f32.f16) ----------------
// MODE 1: h'[t, e*H+n] = probs[t,e]*gelu(x@W1_e + b1_e); also converts its slice of w2
// MODE 2: part[z][t,d] = h'[:, zchunk] @ W2flat[zchunk, :]  (plain stores)
template <int MODE>
__global__ __launch_bounds__(256, 2)
void gemm_kernel(const float* __restrict__ fc1b, const float* __restrict__ w2src) {
    extern __shared__ __half smem[];
    const int tid  = threadIdx.x;
    const int lane = tid & 31;
    const int warp = tid >> 5;
    const int wm = warp >> 2;   // 0..1 (64 rows)
    const int wn = warp & 3;    // 0..3 (32 cols)

    const int bn = blockIdx.x;
    const int bm = blockIdx.y;
    const int bz = blockIdx.z;

    const __half* A;
    const __half* B;
    size_t lda, ldb;
    int kIters;
    if (MODE == 1) {
        A = g_xh + (size_t)bm * BM * D_DIM;                 lda = D_DIM;
        B = g_w1h + (size_t)bz * D_DIM * H_DIM + bn * BN;   ldb = H_DIM;
        kIters = D_DIM / BK;                   // 16
    } else {
        const size_t kOff = (size_t)bz * KCHUNK;            // 4672 per split
        A = g_hb  + (size_t)bm * BM * K2 + kOff;            lda = K2;
        B = g_w2h + kOff * D_DIM + bn * BN;                 ldb = D_DIM;
        kIters = (bz == KSPLIT2 - 1)
                   ? (K2 - (KSPLIT2 - 1) * KCHUNK) / BK     // 74
                   : KCHUNK / BK;                           // 73
    }

    auto load_stage = [&](int s, int kt) {
        const int k0 = kt * BK;
        __half* As = smem + s * STAGE_HALFS;
        __half* Bs = As + A_STAGE_HALFS;
        // A: 128x64 halfs = 1024 x 16B chunks (8 per row)
#pragma unroll
        for (int i = 0; i < 4; i++) {
            int c = tid + i * 256;
            int row = c >> 3, off = (c & 7) * 8;
            const __half* gp = A + (size_t)row * lda + k0 + off;
            unsigned sp = (unsigned)__cvta_generic_to_shared(As + row * (BK + PADA) + off);
            asm volatile("cp.async.cg.shared.global [%0], [%1], 16;" :: "r"(sp), "l"(gp));
        }
        // B: 64x128 halfs = 1024 x 16B chunks (16 per row)
#pragma unroll
        for (int i = 0; i < 4; i++) {
            int c = tid + i * 256;
            int row = c >> 4, off = (c & 15) * 8;
            const __half* gp = B + (size_t)(k0 + row) * ldb + off;
            unsigned sp = (unsigned)__cvta_generic_to_shared(Bs + row * (BN + PADB) + off);
            asm volatile("cp.async.cg.shared.global [%0], [%1], 16;" :: "r"(sp), "l"(gp));
        }
        asm volatile("cp.async.commit_group;" ::);
    };

    float acc[4][4][4];
#pragma unroll
    for (int mf = 0; mf < 4; mf++)
#pragma unroll
        for (int nf = 0; nf < 4; nf++)
#pragma unroll
            for (int i = 0; i < 4; i++) acc[mf][nf][i] = 0.f;

    // prologue: stages 0..1
#pragma unroll
    for (int j = 0; j < NSTAGE - 1; j++) load_stage(j, j);

    if (MODE == 1) {
        // fused w2 fp32->fp16: this CTA's 8192-element slice (4096 CTAs cover 33.5M)
        const int cid = bn + 32 * (bm + 16 * bz);   // 0..4095
        const size_t base = (size_t)cid * 8192;
#pragma unroll
        for (int t = 0; t < 8; t++) {
            size_t i = base + (size_t)(tid + t * 256) * 4;
            float4 v = *reinterpret_cast<const float4*>(w2src + i);
            __half2 h0 = __floats2half2_rn(v.x, v.y);
            __half2 h1 = __floats2half2_rn(v.z, v.w);
            *reinterpret_cast<__half2*>(&g_w2h[i])     = h0;
            *reinterpret_cast<__half2*>(&g_w2h[i + 2]) = h1;
        }
    }

    for (int j = 0; j < kIters; j++) {
        asm volatile("cp.async.wait_group 1;" ::);
        __syncthreads();   // stage j%3 visible; all warps done reading (j-1)%3

        const int p = j + NSTAGE - 1;          // prefetch into stage (j-1)%3
        if (p < kIters) load_stage(p % NSTAGE, p);
        else asm volatile("cp.async.commit_group;" ::);  // keep group count aligned

        const __half* As = smem + (j % NSTAGE) * STAGE_HALFS;
        const __half* Bs = As + A_STAGE_HALFS;

#pragma unroll
        for (int ks = 0; ks < 4; ks++) {
            const int kb = ks * 16;
            unsigned a[4][4];
            unsigned b[4][2];
#pragma unroll
            for (int mf = 0; mf < 4; mf++) {
                int mrow = wm * 64 + mf * 16 + (lane & 15);
                unsigned addr = (unsigned)__cvta_generic_to_shared(
                    As + mrow * (BK + PADA) + kb + (lane >> 4) * 8);
                asm volatile("ldmatrix.sync.aligned.m8n8.x4.shared.b16 {%0,%1,%2,%3}, [%4];"
                             : "=r"(a[mf][0]), "=r"(a[mf][1]), "=r"(a[mf][2]), "=r"(a[mf][3])
                             : "r"(addr));
            }
#pragma unroll
            for (int nf2 = 0; nf2 < 2; nf2++) {
                int ncol = wn * 32 + nf2 * 16 + (lane >> 4) * 8;
                unsigned r0, r1, r2, r3;
                unsigned addr = (unsigned)__cvta_generic_to_shared(
                    Bs + (kb + (lane & 15)) * (BN + PADB) + ncol);
                asm volatile("ldmatrix.sync.aligned.m8n8.x4.trans.shared.b16 {%0,%1,%2,%3}, [%4];"
                             : "=r"(r0), "=r"(r1), "=r"(r2), "=r"(r3)
                             : "r"(addr));
                b[nf2 * 2][0]     = r0; b[nf2 * 2][1]     = r1;
                b[nf2 * 2 + 1][0] = r2; b[nf2 * 2 + 1][1] = r3;
            }
#pragma unroll
            for (int mf = 0; mf < 4; mf++)
#pragma unroll
                for (int nf = 0; nf < 4; nf++) {
                    asm volatile(
                        "mma.sync.aligned.m16n8k16.row.col.f32.f16.f16.f32 "
                        "{%0,%1,%2,%3}, {%4,%5,%6,%7}, {%8,%9}, {%0,%1,%2,%3};"
                        : "+f"(acc[mf][nf][0]), "+f"(acc[mf][nf][1]),
                          "+f"(acc[mf][nf][2]), "+f"(acc[mf][nf][3])
                        : "r"(a[mf][0]), "r"(a[mf][1]), "r"(a[mf][2]), "r"(a[mf][3]),
                          "r"(b[nf][0]), "r"(b[nf][1]));
                }
        }
        // no bottom sync: next iter's top sync orders stage reuse
    }

    // ---------------- epilogue ----------------
    const int mBase = bm * BM + wm * 64;
    const int nBase = bn * BN + wn * 32;
    if (MODE == 1) {
        const int e = bz;
#pragma unroll
        for (int mf = 0; mf < 4; mf++) {
            int r0 = mBase + mf * 16 + (lane >> 2);
#pragma unroll
            for (int nf = 0; nf < 4; nf++) {
                int c0 = nBase + nf * 8 + (lane & 3) * 2;
                float bb0 = fc1b[(size_t)e * H_DIM + c0];
                float bb1 = fc1b[(size_t)e * H_DIM + c0 + 1];
#pragma unroll
                for (int h = 0; h < 2; h++) {
                    int r = r0 + h * 8;
                    float p = g_probs[r * E_NUM + e];
                    float v0 = gelu_exact(acc[mf][nf][h * 2 + 0] + bb0) * p;
                    float v1 = gelu_exact(acc[mf][nf][h * 2 + 1] + bb1) * p;
                    *reinterpret_cast<__half2*>(
                        &g_hb[(size_t)r * K2 + (size_t)e * H_DIM + c0]) =
                        __floats2half2_rn(v0, v1);
                }
            }
        }
    } else {
        float* part = g_part + (size_t)bz * T_TOK * D_DIM;
#pragma unroll
        for (int mf = 0; mf < 4; mf++) {
            int r0 = mBase + mf * 16 + (lane >> 2);
#pragma unroll
            for (int nf = 0; nf < 4; nf++) {
                int c0 = nBase + nf * 8 + (lane & 3) * 2;
                *reinterpret_cast<float2*>(&part[(size_t)r0 * D_DIM + c0]) =
                    make_float2(acc[mf][nf][0], acc[mf][nf][1]);
                *reinterpret_cast<float2*>(&part[(size_t)(r0 + 8) * D_DIM + c0]) =
                    make_float2(acc[mf][nf][2], acc[mf][nf][3]);
            }
        }
    }
}

// ---------------- launch ----------------
extern "C" void kernel_launch(void* const* d_in, const int* in_sizes, int n_in,
                              void* d_out, int out_size) {
    const float* x   = (const float*)d_in[0];
    const float* rw  = (const float*)d_in[1];
    const float* rb  = (const float*)d_in[2];
    const float* w1  = (const float*)d_in[3];
    const float* b1  = (const float*)d_in[4];
    const float* w2  = (const float*)d_in[5];
    const float* b2  = (const float*)d_in[6];

    float* y      = (float*)d_out;                 // [T, D]
    float* dprobs = y + (size_t)T_TOK * D_DIM;     // [T, E]

    cudaFuncSetAttribute(gemm_kernel<1>, cudaFuncAttributeMaxDynamicSharedMemorySize, SMEM_BYTES);
    cudaFuncSetAttribute(gemm_kernel<2>, cudaFuncAttributeMaxDynamicSharedMemorySize, SMEM_BYTES);

    prep_kernel<<<NW1 / 4 / 256 + NX / 4 / 256, 256>>>(w1, x);   // w1 + x -> fp16
    router_kernel<<<T_TOK / 8, 256>>>(x, rw, rb, dprobs);

    {
        dim3 g(H_DIM / BN, T_TOK / BM, E_NUM);     // (32, 16, 8) = 4096 CTAs
        gemm_kernel<1><<<g, 256, SMEM_BYTES>>>(b1, w2);   // also converts w2
    }
    {
        dim3 g(D_DIM / BN, T_TOK / BM, KSPLIT2);   // (8, 16, 7) = 896 CTAs
        gemm_kernel<2><<<g, 256, SMEM_BYTES>>>(nullptr, nullptr);
    }
    combine_kernel<<<(T_TOK * D_DIM) / 4 / 256, 256>>>(b2, y);
}